// round 14
// baseline (speedup 1.0000x reference)
#include <cuda_runtime.h>
#include <cuda_bf16.h>
#include <cstdint>
#include <cstddef>

#define N_TOKENS 1024
#define IN_F 4096
#define OUT_F 4096

#define TM 128
#define TN 128
#define KC 32
#define NKC (IN_F / KC)        // 128
#define STAGES 3
// stage: Ah 8K | Al 8K | Bh 8K | Bl 8K = 32KB
#define ST_AH 0
#define ST_AL 8192
#define ST_BH 16384
#define ST_BL 24576
#define STAGE_BYTES 32768
#define SMEM_TOTAL (STAGES * STAGE_BYTES)   // 96 KB -> 2 CTAs/SM

// ---------------- scratch (static device globals; no runtime allocation) ----
// X: row-major [token][k].  W: BLOCK-MAJOR [b][o][8] (16B chunk idx = b*4096+o)
__device__ __nv_bfloat16 g_Xh[(size_t)N_TOKENS * IN_F];
__device__ __nv_bfloat16 g_Xl[(size_t)N_TOKENS * IN_F];
__device__ __nv_bfloat16 g_Wh[(size_t)OUT_F * IN_F];
__device__ __nv_bfloat16 g_Wl[(size_t)OUT_F * IN_F];

// ---------------- helpers ----------------------------------------------------
__device__ __forceinline__ uint32_t smem_u32(const void* p) {
    uint32_t a;
    asm("{ .reg .u64 t; cvta.to.shared.u64 t, %1; cvt.u32.u64 %0, t; }"
        : "=r"(a) : "l"(p));
    return a;
}

__device__ __forceinline__ uint32_t pack_bf2(__nv_bfloat16 a, __nv_bfloat16 b) {
    __nv_bfloat162 t = __halves2bfloat162(a, b);
    return *reinterpret_cast<uint32_t*>(&t);
}

__device__ __forceinline__ void cp16(uint32_t s, const void* g) {
    asm volatile("cp.async.cg.shared.global [%0], [%1], 16;"
                 :: "r"(s), "l"(g));
}

__device__ __forceinline__ void ldsm4(uint32_t* r, uint32_t a) {
    asm volatile("ldmatrix.sync.aligned.m8n8.x4.shared.b16 {%0,%1,%2,%3}, [%4];"
                 : "=r"(r[0]), "=r"(r[1]), "=r"(r[2]), "=r"(r[3]) : "r"(a));
}

__device__ __forceinline__ void mma16816(float* d, const uint32_t* a,
                                         const uint32_t* b) {
    asm volatile(
        "mma.sync.aligned.m16n8k16.row.col.f32.bf16.bf16.f32 "
        "{%0,%1,%2,%3}, {%4,%5,%6,%7}, {%8,%9}, {%0,%1,%2,%3};"
        : "+f"(d[0]), "+f"(d[1]), "+f"(d[2]), "+f"(d[3])
        : "r"(a[0]), "r"(a[1]), "r"(a[2]), "r"(a[3]), "r"(b[0]), "r"(b[1]));
}

// ---------------- kernel 1: fused prep (convert x  +  decode W) -------------
#define PREP_X_BLOCKS 4096
#define PREP_W_BLOCKS 8192
__global__ void __launch_bounds__(256)
prep_kernel(const float* __restrict__ x,
            const float* __restrict__ centroids,
            const int* __restrict__ assignments) {
    if (blockIdx.x < PREP_X_BLOCKS) {
        int i = blockIdx.x * 256 + threadIdx.x;
        float4 v = reinterpret_cast<const float4*>(x)[i];
        __nv_bfloat16 h0 = __float2bfloat16(v.x), h1 = __float2bfloat16(v.y);
        __nv_bfloat16 h2 = __float2bfloat16(v.z), h3 = __float2bfloat16(v.w);
        __nv_bfloat16 l0 = __float2bfloat16(v.x - __bfloat162float(h0));
        __nv_bfloat16 l1 = __float2bfloat16(v.y - __bfloat162float(h1));
        __nv_bfloat16 l2 = __float2bfloat16(v.z - __bfloat162float(h2));
        __nv_bfloat16 l3 = __float2bfloat16(v.w - __bfloat162float(h3));
        uint2 uh; uh.x = pack_bf2(h0, h1); uh.y = pack_bf2(h2, h3);
        uint2 ul; ul.x = pack_bf2(l0, l1); ul.y = pack_bf2(l2, l3);
        reinterpret_cast<uint2*>(g_Xh)[i] = uh;
        reinterpret_cast<uint2*>(g_Xl)[i] = ul;
    } else {
        int idx = (blockIdx.x - PREP_X_BLOCKS) * 256 + threadIdx.x;
        int c = __ldg(&assignments[idx]);
        const float4* cp =
            reinterpret_cast<const float4*>(centroids + (size_t)c * 8);
        float4 v0 = cp[0];
        float4 v1 = cp[1];
        float f[8] = {v0.x, v0.y, v0.z, v0.w, v1.x, v1.y, v1.z, v1.w};
        __nv_bfloat16 h[8], l[8];
#pragma unroll
        for (int j = 0; j < 8; j++) {
            h[j] = __float2bfloat16(f[j]);
            l[j] = __float2bfloat16(f[j] - __bfloat162float(h[j]));
        }
        uint4 uh, ul;
        uh.x = pack_bf2(h[0], h[1]); uh.y = pack_bf2(h[2], h[3]);
        uh.z = pack_bf2(h[4], h[5]); uh.w = pack_bf2(h[6], h[7]);
        ul.x = pack_bf2(l[0], l[1]); ul.y = pack_bf2(l[2], l[3]);
        ul.z = pack_bf2(l[4], l[5]); ul.w = pack_bf2(l[6], l[7]);
        reinterpret_cast<uint4*>(g_Wh)[idx] = uh;
        reinterpret_cast<uint4*>(g_Wl)[idx] = ul;
    }
}

// ---------------- kernel 2: mma.sync bf16x3 GEMM + bias ----------------------
// CTA tile 128x128, 8 warps (4x2), warp tile 32x64, 3-stage cp.async,
// 2 CTAs co-resident per SM for cross-CTA bubble hiding.
// smem rows: 64B = 4 x 16B chunks; swizzle chunk' = chunk ^ ((row>>1)&3).
__global__ void __launch_bounds__(256, 2)
gemm_kernel(const float* __restrict__ bias, float* __restrict__ out) {
    extern __shared__ char smem[];
    uint32_t sb = smem_u32(smem);
    int tid = threadIdx.x, lane = tid & 31, wid = tid >> 5;
    int n0 = blockIdx.x * TN;
    int m0 = blockIdx.y * TM;
    int wm = (wid >> 1) * 32;   // warp M offset (0..96)
    int wn = (wid & 1) * 64;    // warp N offset (0/64)

    // ---- cp.async load mapping: 256 threads, 8 x 16B each per stage ----
    int arow = tid >> 1;                 // 0..127
    int ach = (tid & 1) * 2;             // chunks {0,1} or {2,3}
    int ars = (arow >> 1) & 3;
    uint32_t aoff0 = (uint32_t)(arow * 64 + (((ach + 0) ^ ars) << 4));
    uint32_t aoff1 = (uint32_t)(arow * 64 + (((ach + 1) ^ ars) << 4));
    const __nv_bfloat16* gAh = g_Xh + (size_t)(m0 + arow) * IN_F + ach * 8;
    const __nv_bfloat16* gAl = g_Xl + (size_t)(m0 + arow) * IN_F + ach * 8;

    // B block-major: chunk (block b, row o) at uint4 index b*OUT_F + o.
    // Thread covers row arow, block offsets ach, ach+1 within the KC window.
    size_t bbase0 = (size_t)(ach + 0) * OUT_F + (n0 + arow);
    size_t bbase1 = (size_t)(ach + 1) * OUT_F + (n0 + arow);

    // ---- ldmatrix fixed row indices ----
    int rA[2], rsA[2];
#pragma unroll
    for (int i = 0; i < 2; i++) {
        rA[i] = wm + i * 16 + (lane & 15);
        rsA[i] = (rA[i] >> 1) & 3;
    }
    int rB[4], rsB[4];
#pragma unroll
    for (int j2 = 0; j2 < 4; j2++) {
        rB[j2] = wn + j2 * 16 + ((lane >> 4) & 1) * 8 + (lane & 7);
        rsB[j2] = (rB[j2] >> 1) & 3;
    }
    int chA_lo = (lane >> 4);        // 0/1
    int chB_lo = ((lane >> 3) & 1);  // 0/1

    float acc[2][8][4];
#pragma unroll
    for (int i = 0; i < 2; i++)
#pragma unroll
        for (int j = 0; j < 8; j++)
#pragma unroll
            for (int e = 0; e < 4; e++) acc[i][j][e] = 0.f;

    auto load_stage = [&](uint32_t st, int kc) {
        int k0 = kc * KC;
        size_t boffk = (size_t)(kc * 4) * OUT_F;   // 4 blocks per KC window
        cp16(st + ST_AH + aoff0, gAh + k0);
        cp16(st + ST_AH + aoff1, gAh + k0 + 8);
        cp16(st + ST_AL + aoff0, gAl + k0);
        cp16(st + ST_AL + aoff1, gAl + k0 + 8);
        cp16(st + ST_BH + aoff0, reinterpret_cast<const uint4*>(g_Wh) + bbase0 + boffk);
        cp16(st + ST_BH + aoff1, reinterpret_cast<const uint4*>(g_Wh) + bbase1 + boffk);
        cp16(st + ST_BL + aoff0, reinterpret_cast<const uint4*>(g_Wl) + bbase0 + boffk);
        cp16(st + ST_BL + aoff1, reinterpret_cast<const uint4*>(g_Wl) + bbase1 + boffk);
        asm volatile("cp.async.commit_group;");
    };

    // ---- prologue: fill STAGES-1 stages ----
#pragma unroll
    for (int s = 0; s < STAGES - 1; s++)
        load_stage(sb + s * STAGE_BYTES, s);

    for (int kc = 0; kc < NKC; kc++) {
        asm volatile("cp.async.wait_group %0;" :: "n"(STAGES - 2));
        __syncthreads();
        uint32_t st = sb + (kc % STAGES) * STAGE_BYTES;

#pragma unroll
        for (int ks = 0; ks < 2; ks++) {
            uint32_t Ah[2][4], Al[2][4];
#pragma unroll
            for (int i = 0; i < 2; i++) {
                int ch = ks * 2 + chA_lo;
                uint32_t off = (uint32_t)(rA[i] * 64 + ((ch ^ rsA[i]) << 4));
                ldsm4(Ah[i], st + ST_AH + off);
                ldsm4(Al[i], st + ST_AL + off);
            }
#pragma unroll
            for (int j2 = 0; j2 < 4; j2++) {
                uint32_t Bh[4], Bl[4];
                int ch = ks * 2 + chB_lo;
                uint32_t off = (uint32_t)(rB[j2] * 64 + ((ch ^ rsB[j2]) << 4));
                ldsm4(Bh, st + ST_BH + off);
                ldsm4(Bl, st + ST_BL + off);
                float* d00 = acc[0][j2 * 2];
                float* d01 = acc[0][j2 * 2 + 1];
                float* d10 = acc[1][j2 * 2];
                float* d11 = acc[1][j2 * 2 + 1];
                // term-major: same-accumulator reuse distance = 4 MMAs
                mma16816(d00, Ah[0], &Bh[0]);
                mma16816(d01, Ah[0], &Bh[2]);
                mma16816(d10, Ah[1], &Bh[0]);
                mma16816(d11, Ah[1], &Bh[2]);
                mma16816(d00, Ah[0], &Bl[0]);
                mma16816(d01, Ah[0], &Bl[2]);
                mma16816(d10, Ah[1], &Bl[0]);
                mma16816(d11, Ah[1], &Bl[2]);
                mma16816(d00, Al[0], &Bh[0]);
                mma16816(d01, Al[0], &Bh[2]);
                mma16816(d10, Al[1], &Bh[0]);
                mma16816(d11, Al[1], &Bh[2]);
            }
        }

        int nk = kc + STAGES - 1;
        if (nk < NKC)
            load_stage(sb + (nk % STAGES) * STAGE_BYTES, nk);
        else
            asm volatile("cp.async.commit_group;");
    }

    // ---- epilogue: bias add + fp32 stores ----
#pragma unroll
    for (int i = 0; i < 2; i++) {
        int r = m0 + wm + i * 16 + (lane >> 2);
        float* row0 = out + (size_t)r * OUT_F;
        float* row1 = row0 + (size_t)8 * OUT_F;
#pragma unroll
        for (int j = 0; j < 8; j++) {
            int c = n0 + wn + j * 8 + 2 * (lane & 3);
            float b0 = __ldg(&bias[c]), b1 = __ldg(&bias[c + 1]);
            float2 v0 = make_float2(acc[i][j][0] + b0, acc[i][j][1] + b1);
            float2 v1 = make_float2(acc[i][j][2] + b0, acc[i][j][3] + b1);
            *reinterpret_cast<float2*>(row0 + c) = v0;
            *reinterpret_cast<float2*>(row1 + c) = v1;
        }
    }
}

// ---------------- launch -----------------------------------------------------
extern "C" void kernel_launch(void* const* d_in, const int* in_sizes, int n_in,
                              void* d_out, int out_size) {
    const float* x           = (const float*)d_in[0];
    const float* centroids   = (const float*)d_in[1];
    const float* bias        = (const float*)d_in[2];
    const int*   assignments = (const int*)d_in[3];
    float* out = (float*)d_out;

    cudaFuncSetAttribute(gemm_kernel,
                         cudaFuncAttributeMaxDynamicSharedMemorySize, SMEM_TOTAL);

    prep_kernel<<<PREP_X_BLOCKS + PREP_W_BLOCKS, 256>>>(x, centroids, assignments);
    gemm_kernel<<<dim3(OUT_F / TN, N_TOKENS / TM), 256, SMEM_TOTAL>>>(bias, out);
}

// round 15
// speedup vs baseline: 1.0039x; 1.0039x over previous
#include <cuda_runtime.h>
#include <cuda_bf16.h>
#include <cstdint>
#include <cstddef>

#define N_TOKENS 1024
#define IN_F 4096
#define OUT_F 4096

#define TM 128
#define TN 128
#define KC 32
#define NKC (IN_F / KC)        // 128
#define STAGES 3
// stage: Ah 8K | Al 8K | Bh 8K | Bl 8K = 32KB
#define ST_AH 0
#define ST_AL 8192
#define ST_BH 16384
#define ST_BL 24576
#define STAGE_BYTES 32768
#define SMEM_TOTAL (STAGES * STAGE_BYTES)   // 96 KB -> 2 CTAs/SM

// ---------------- scratch (static device globals; no runtime allocation) ----
// X: row-major [token][k].  W: BLOCK-MAJOR [b][o][8] (16B chunk idx = b*4096+o)
__device__ __nv_bfloat16 g_Xh[(size_t)N_TOKENS * IN_F];
__device__ __nv_bfloat16 g_Xl[(size_t)N_TOKENS * IN_F];
__device__ __nv_bfloat16 g_Wh[(size_t)OUT_F * IN_F];
__device__ __nv_bfloat16 g_Wl[(size_t)OUT_F * IN_F];

// ---------------- helpers ----------------------------------------------------
__device__ __forceinline__ uint32_t smem_u32(const void* p) {
    uint32_t a;
    asm("{ .reg .u64 t; cvta.to.shared.u64 t, %1; cvt.u32.u64 %0, t; }"
        : "=r"(a) : "l"(p));
    return a;
}

__device__ __forceinline__ uint32_t pack_bf2(__nv_bfloat16 a, __nv_bfloat16 b) {
    __nv_bfloat162 t = __halves2bfloat162(a, b);
    return *reinterpret_cast<uint32_t*>(&t);
}

__device__ __forceinline__ void cp16(uint32_t s, const void* g) {
    asm volatile("cp.async.cg.shared.global [%0], [%1], 16;"
                 :: "r"(s), "l"(g));
}

__device__ __forceinline__ void ldsm4(uint32_t* r, uint32_t a) {
    asm volatile("ldmatrix.sync.aligned.m8n8.x4.shared.b16 {%0,%1,%2,%3}, [%4];"
                 : "=r"(r[0]), "=r"(r[1]), "=r"(r[2]), "=r"(r[3]) : "r"(a));
}

__device__ __forceinline__ void mma16816(float* d, const uint32_t* a,
                                         const uint32_t* b) {
    asm volatile(
        "mma.sync.aligned.m16n8k16.row.col.f32.bf16.bf16.f32 "
        "{%0,%1,%2,%3}, {%4,%5,%6,%7}, {%8,%9}, {%0,%1,%2,%3};"
        : "+f"(d[0]), "+f"(d[1]), "+f"(d[2]), "+f"(d[3])
        : "r"(a[0]), "r"(a[1]), "r"(a[2]), "r"(a[3]), "r"(b[0]), "r"(b[1]));
}

// ---------------- kernel 1: fused prep (convert x  +  decode W) -------------
#define PREP_X_BLOCKS 4096
#define PREP_W_BLOCKS 8192
__global__ void __launch_bounds__(256)
prep_kernel(const float* __restrict__ x,
            const float* __restrict__ centroids,
            const int* __restrict__ assignments) {
    if (blockIdx.x < PREP_X_BLOCKS) {
        int i = blockIdx.x * 256 + threadIdx.x;
        float4 v = reinterpret_cast<const float4*>(x)[i];
        __nv_bfloat16 h0 = __float2bfloat16(v.x), h1 = __float2bfloat16(v.y);
        __nv_bfloat16 h2 = __float2bfloat16(v.z), h3 = __float2bfloat16(v.w);
        __nv_bfloat16 l0 = __float2bfloat16(v.x - __bfloat162float(h0));
        __nv_bfloat16 l1 = __float2bfloat16(v.y - __bfloat162float(h1));
        __nv_bfloat16 l2 = __float2bfloat16(v.z - __bfloat162float(h2));
        __nv_bfloat16 l3 = __float2bfloat16(v.w - __bfloat162float(h3));
        uint2 uh; uh.x = pack_bf2(h0, h1); uh.y = pack_bf2(h2, h3);
        uint2 ul; ul.x = pack_bf2(l0, l1); ul.y = pack_bf2(l2, l3);
        reinterpret_cast<uint2*>(g_Xh)[i] = uh;
        reinterpret_cast<uint2*>(g_Xl)[i] = ul;
    } else {
        int idx = (blockIdx.x - PREP_X_BLOCKS) * 256 + threadIdx.x;
        int c = __ldg(&assignments[idx]);
        const float4* cp =
            reinterpret_cast<const float4*>(centroids + (size_t)c * 8);
        float4 v0 = cp[0];
        float4 v1 = cp[1];
        float f[8] = {v0.x, v0.y, v0.z, v0.w, v1.x, v1.y, v1.z, v1.w};
        __nv_bfloat16 h[8], l[8];
#pragma unroll
        for (int j = 0; j < 8; j++) {
            h[j] = __float2bfloat16(f[j]);
            l[j] = __float2bfloat16(f[j] - __bfloat162float(h[j]));
        }
        uint4 uh, ul;
        uh.x = pack_bf2(h[0], h[1]); uh.y = pack_bf2(h[2], h[3]);
        uh.z = pack_bf2(h[4], h[5]); uh.w = pack_bf2(h[6], h[7]);
        ul.x = pack_bf2(l[0], l[1]); ul.y = pack_bf2(l[2], l[3]);
        ul.z = pack_bf2(l[4], l[5]); ul.w = pack_bf2(l[6], l[7]);
        reinterpret_cast<uint4*>(g_Wh)[idx] = uh;
        reinterpret_cast<uint4*>(g_Wl)[idx] = ul;
    }
}

// ---------------- kernel 2: mma.sync bf16x3 GEMM + bias ----------------------
// CTA tile 128x128, 8 warps (4x2), warp tile 32x64, 3-stage cp.async,
// 2 CTAs co-resident per SM for cross-CTA bubble hiding.
// smem rows: 64B = 4 x 16B chunks; swizzle chunk' = chunk ^ ((row>>1)&3).
__global__ void __launch_bounds__(256, 2)
gemm_kernel(const float* __restrict__ bias, float* __restrict__ out) {
    extern __shared__ char smem[];
    uint32_t sb = smem_u32(smem);
    int tid = threadIdx.x, lane = tid & 31, wid = tid >> 5;
    int n0 = blockIdx.x * TN;
    int m0 = blockIdx.y * TM;
    int wm = (wid >> 1) * 32;   // warp M offset (0..96)
    int wn = (wid & 1) * 64;    // warp N offset (0/64)

    // ---- cp.async load mapping: 256 threads, 8 x 16B each per stage ----
    int arow = tid >> 1;                 // 0..127
    int ach = (tid & 1) * 2;             // chunks {0,1} or {2,3}
    int ars = (arow >> 1) & 3;
    uint32_t aoff0 = (uint32_t)(arow * 64 + (((ach + 0) ^ ars) << 4));
    uint32_t aoff1 = (uint32_t)(arow * 64 + (((ach + 1) ^ ars) << 4));
    const __nv_bfloat16* gAh = g_Xh + (size_t)(m0 + arow) * IN_F + ach * 8;
    const __nv_bfloat16* gAl = g_Xl + (size_t)(m0 + arow) * IN_F + ach * 8;

    // B block-major: chunk (block b, row o) at uint4 index b*OUT_F + o.
    // Thread covers row arow, block offsets ach, ach+1 within the KC window.
    size_t bbase0 = (size_t)(ach + 0) * OUT_F + (n0 + arow);
    size_t bbase1 = (size_t)(ach + 1) * OUT_F + (n0 + arow);

    // ---- ldmatrix fixed row indices ----
    int rA[2], rsA[2];
#pragma unroll
    for (int i = 0; i < 2; i++) {
        rA[i] = wm + i * 16 + (lane & 15);
        rsA[i] = (rA[i] >> 1) & 3;
    }
    int rB[4], rsB[4];
#pragma unroll
    for (int j2 = 0; j2 < 4; j2++) {
        rB[j2] = wn + j2 * 16 + ((lane >> 4) & 1) * 8 + (lane & 7);
        rsB[j2] = (rB[j2] >> 1) & 3;
    }
    int chA_lo = (lane >> 4);        // 0/1
    int chB_lo = ((lane >> 3) & 1);  // 0/1

    float acc[2][8][4];
#pragma unroll
    for (int i = 0; i < 2; i++)
#pragma unroll
        for (int j = 0; j < 8; j++)
#pragma unroll
            for (int e = 0; e < 4; e++) acc[i][j][e] = 0.f;

    auto load_stage = [&](uint32_t st, int kc) {
        int k0 = kc * KC;
        size_t boffk = (size_t)(kc * 4) * OUT_F;   // 4 blocks per KC window
        cp16(st + ST_AH + aoff0, gAh + k0);
        cp16(st + ST_AH + aoff1, gAh + k0 + 8);
        cp16(st + ST_AL + aoff0, gAl + k0);
        cp16(st + ST_AL + aoff1, gAl + k0 + 8);
        cp16(st + ST_BH + aoff0, reinterpret_cast<const uint4*>(g_Wh) + bbase0 + boffk);
        cp16(st + ST_BH + aoff1, reinterpret_cast<const uint4*>(g_Wh) + bbase1 + boffk);
        cp16(st + ST_BL + aoff0, reinterpret_cast<const uint4*>(g_Wl) + bbase0 + boffk);
        cp16(st + ST_BL + aoff1, reinterpret_cast<const uint4*>(g_Wl) + bbase1 + boffk);
        asm volatile("cp.async.commit_group;");
    };

    // ---- prologue: fill STAGES-1 stages ----
#pragma unroll
    for (int s = 0; s < STAGES - 1; s++)
        load_stage(sb + s * STAGE_BYTES, s);

    for (int kc = 0; kc < NKC; kc++) {
        asm volatile("cp.async.wait_group %0;" :: "n"(STAGES - 2));
        __syncthreads();
        uint32_t st = sb + (kc % STAGES) * STAGE_BYTES;

#pragma unroll
        for (int ks = 0; ks < 2; ks++) {
            uint32_t Ah[2][4], Al[2][4];
#pragma unroll
            for (int i = 0; i < 2; i++) {
                int ch = ks * 2 + chA_lo;
                uint32_t off = (uint32_t)(rA[i] * 64 + ((ch ^ rsA[i]) << 4));
                ldsm4(Ah[i], st + ST_AH + off);
                ldsm4(Al[i], st + ST_AL + off);
            }
#pragma unroll
            for (int j2 = 0; j2 < 4; j2++) {
                uint32_t Bh[4], Bl[4];
                int ch = ks * 2 + chB_lo;
                uint32_t off = (uint32_t)(rB[j2] * 64 + ((ch ^ rsB[j2]) << 4));
                ldsm4(Bh, st + ST_BH + off);
                ldsm4(Bl, st + ST_BL + off);
                float* d00 = acc[0][j2 * 2];
                float* d01 = acc[0][j2 * 2 + 1];
                float* d10 = acc[1][j2 * 2];
                float* d11 = acc[1][j2 * 2 + 1];
                // term-major: same-accumulator reuse distance = 4 MMAs
                mma16816(d00, Ah[0], &Bh[0]);
                mma16816(d01, Ah[0], &Bh[2]);
                mma16816(d10, Ah[1], &Bh[0]);
                mma16816(d11, Ah[1], &Bh[2]);
                mma16816(d00, Ah[0], &Bl[0]);
                mma16816(d01, Ah[0], &Bl[2]);
                mma16816(d10, Ah[1], &Bl[0]);
                mma16816(d11, Ah[1], &Bl[2]);
                mma16816(d00, Al[0], &Bh[0]);
                mma16816(d01, Al[0], &Bh[2]);
                mma16816(d10, Al[1], &Bh[0]);
                mma16816(d11, Al[1], &Bh[2]);
            }
        }

        int nk = kc + STAGES - 1;
        if (nk < NKC)
            load_stage(sb + (nk % STAGES) * STAGE_BYTES, nk);
        else
            asm volatile("cp.async.commit_group;");
    }

    // ---- epilogue: bias add + fp32 stores ----
#pragma unroll
    for (int i = 0; i < 2; i++) {
        int r = m0 + wm + i * 16 + (lane >> 2);
        float* row0 = out + (size_t)r * OUT_F;
        float* row1 = row0 + (size_t)8 * OUT_F;
#pragma unroll
        for (int j = 0; j < 8; j++) {
            int c = n0 + wn + j * 8 + 2 * (lane & 3);
            float b0 = __ldg(&bias[c]), b1 = __ldg(&bias[c + 1]);
            float2 v0 = make_float2(acc[i][j][0] + b0, acc[i][j][1] + b1);
            float2 v1 = make_float2(acc[i][j][2] + b0, acc[i][j][3] + b1);
            *reinterpret_cast<float2*>(row0 + c) = v0;
            *reinterpret_cast<float2*>(row1 + c) = v1;
        }
    }
}

// ---------------- launch -----------------------------------------------------
extern "C" void kernel_launch(void* const* d_in, const int* in_sizes, int n_in,
                              void* d_out, int out_size) {
    const float* x           = (const float*)d_in[0];
    const float* centroids   = (const float*)d_in[1];
    const float* bias        = (const float*)d_in[2];
    const int*   assignments = (const int*)d_in[3];
    float* out = (float*)d_out;

    cudaFuncSetAttribute(gemm_kernel,
                         cudaFuncAttributeMaxDynamicSharedMemorySize, SMEM_TOTAL);

    prep_kernel<<<PREP_X_BLOCKS + PREP_W_BLOCKS, 256>>>(x, centroids, assignments);
    gemm_kernel<<<dim3(OUT_F / TN, N_TOKENS / TM), 256, SMEM_TOTAL>>>(bias, out);
}

// round 16
// speedup vs baseline: 1.0040x; 1.0001x over previous
#include <cuda_runtime.h>
#include <cuda_bf16.h>
#include <cstdint>
#include <cstddef>

#define N_TOKENS 1024
#define IN_F 4096
#define OUT_F 4096

#define TM 128
#define TN 128
#define KC 32
#define NKC (IN_F / KC)        // 128
#define STAGES 3
// stage: Ah 8K | Al 8K | Bh 8K | Bl 8K = 32KB
#define ST_AH 0
#define ST_AL 8192
#define ST_BH 16384
#define ST_BL 24576
#define STAGE_BYTES 32768
#define SMEM_TOTAL (STAGES * STAGE_BYTES)   // 96 KB -> 2 CTAs/SM

// ---------------- scratch (static device globals; no runtime allocation) ----
// X: row-major [token][k].  W: BLOCK-MAJOR [b][o][8] (16B chunk idx = b*4096+o)
__device__ __nv_bfloat16 g_Xh[(size_t)N_TOKENS * IN_F];
__device__ __nv_bfloat16 g_Xl[(size_t)N_TOKENS * IN_F];
__device__ __nv_bfloat16 g_Wh[(size_t)OUT_F * IN_F];
__device__ __nv_bfloat16 g_Wl[(size_t)OUT_F * IN_F];

// ---------------- helpers ----------------------------------------------------
__device__ __forceinline__ uint32_t smem_u32(const void* p) {
    uint32_t a;
    asm("{ .reg .u64 t; cvta.to.shared.u64 t, %1; cvt.u32.u64 %0, t; }"
        : "=r"(a) : "l"(p));
    return a;
}

__device__ __forceinline__ uint32_t pack_bf2(__nv_bfloat16 a, __nv_bfloat16 b) {
    __nv_bfloat162 t = __halves2bfloat162(a, b);
    return *reinterpret_cast<uint32_t*>(&t);
}

__device__ __forceinline__ void cp16(uint32_t s, const void* g) {
    asm volatile("cp.async.cg.shared.global [%0], [%1], 16;"
                 :: "r"(s), "l"(g));
}

__device__ __forceinline__ void ldsm4(uint32_t* r, uint32_t a) {
    asm volatile("ldmatrix.sync.aligned.m8n8.x4.shared.b16 {%0,%1,%2,%3}, [%4];"
                 : "=r"(r[0]), "=r"(r[1]), "=r"(r[2]), "=r"(r[3]) : "r"(a));
}

__device__ __forceinline__ void mma16816(float* d, const uint32_t* a,
                                         const uint32_t* b) {
    asm volatile(
        "mma.sync.aligned.m16n8k16.row.col.f32.bf16.bf16.f32 "
        "{%0,%1,%2,%3}, {%4,%5,%6,%7}, {%8,%9}, {%0,%1,%2,%3};"
        : "+f"(d[0]), "+f"(d[1]), "+f"(d[2]), "+f"(d[3])
        : "r"(a[0]), "r"(a[1]), "r"(a[2]), "r"(a[3]), "r"(b[0]), "r"(b[1]));
}

// ---------------- kernel 1: fused prep (convert x  +  decode W) -------------
#define PREP_X_BLOCKS 4096
#define PREP_W_BLOCKS 8192
__global__ void __launch_bounds__(256)
prep_kernel(const float* __restrict__ x,
            const float* __restrict__ centroids,
            const int* __restrict__ assignments) {
    if (blockIdx.x < PREP_X_BLOCKS) {
        int i = blockIdx.x * 256 + threadIdx.x;
        float4 v = reinterpret_cast<const float4*>(x)[i];
        __nv_bfloat16 h0 = __float2bfloat16(v.x), h1 = __float2bfloat16(v.y);
        __nv_bfloat16 h2 = __float2bfloat16(v.z), h3 = __float2bfloat16(v.w);
        __nv_bfloat16 l0 = __float2bfloat16(v.x - __bfloat162float(h0));
        __nv_bfloat16 l1 = __float2bfloat16(v.y - __bfloat162float(h1));
        __nv_bfloat16 l2 = __float2bfloat16(v.z - __bfloat162float(h2));
        __nv_bfloat16 l3 = __float2bfloat16(v.w - __bfloat162float(h3));
        uint2 uh; uh.x = pack_bf2(h0, h1); uh.y = pack_bf2(h2, h3);
        uint2 ul; ul.x = pack_bf2(l0, l1); ul.y = pack_bf2(l2, l3);
        reinterpret_cast<uint2*>(g_Xh)[i] = uh;
        reinterpret_cast<uint2*>(g_Xl)[i] = ul;
    } else {
        int idx = (blockIdx.x - PREP_X_BLOCKS) * 256 + threadIdx.x;
        int c = __ldg(&assignments[idx]);
        const float4* cp =
            reinterpret_cast<const float4*>(centroids + (size_t)c * 8);
        float4 v0 = cp[0];
        float4 v1 = cp[1];
        float f[8] = {v0.x, v0.y, v0.z, v0.w, v1.x, v1.y, v1.z, v1.w};
        __nv_bfloat16 h[8], l[8];
#pragma unroll
        for (int j = 0; j < 8; j++) {
            h[j] = __float2bfloat16(f[j]);
            l[j] = __float2bfloat16(f[j] - __bfloat162float(h[j]));
        }
        uint4 uh, ul;
        uh.x = pack_bf2(h[0], h[1]); uh.y = pack_bf2(h[2], h[3]);
        uh.z = pack_bf2(h[4], h[5]); uh.w = pack_bf2(h[6], h[7]);
        ul.x = pack_bf2(l[0], l[1]); ul.y = pack_bf2(l[2], l[3]);
        ul.z = pack_bf2(l[4], l[5]); ul.w = pack_bf2(l[6], l[7]);
        reinterpret_cast<uint4*>(g_Wh)[idx] = uh;
        reinterpret_cast<uint4*>(g_Wl)[idx] = ul;
    }
}

// ---------------- kernel 2: mma.sync bf16x3 GEMM + bias ----------------------
// CTA tile 128x128, 8 warps (4x2), warp tile 32x64, 3-stage cp.async,
// 2 CTAs co-resident per SM for cross-CTA bubble hiding.
// smem rows: 64B = 4 x 16B chunks; swizzle chunk' = chunk ^ ((row>>1)&3).
__global__ void __launch_bounds__(256, 2)
gemm_kernel(const float* __restrict__ bias, float* __restrict__ out) {
    extern __shared__ char smem[];
    uint32_t sb = smem_u32(smem);
    int tid = threadIdx.x, lane = tid & 31, wid = tid >> 5;
    int n0 = blockIdx.x * TN;
    int m0 = blockIdx.y * TM;
    int wm = (wid >> 1) * 32;   // warp M offset (0..96)
    int wn = (wid & 1) * 64;    // warp N offset (0/64)

    // ---- cp.async load mapping: 256 threads, 8 x 16B each per stage ----
    int arow = tid >> 1;                 // 0..127
    int ach = (tid & 1) * 2;             // chunks {0,1} or {2,3}
    int ars = (arow >> 1) & 3;
    uint32_t aoff0 = (uint32_t)(arow * 64 + (((ach + 0) ^ ars) << 4));
    uint32_t aoff1 = (uint32_t)(arow * 64 + (((ach + 1) ^ ars) << 4));
    const __nv_bfloat16* gAh = g_Xh + (size_t)(m0 + arow) * IN_F + ach * 8;
    const __nv_bfloat16* gAl = g_Xl + (size_t)(m0 + arow) * IN_F + ach * 8;

    // B block-major: chunk (block b, row o) at uint4 index b*OUT_F + o.
    // Thread covers row arow, block offsets ach, ach+1 within the KC window.
    size_t bbase0 = (size_t)(ach + 0) * OUT_F + (n0 + arow);
    size_t bbase1 = (size_t)(ach + 1) * OUT_F + (n0 + arow);

    // ---- ldmatrix fixed row indices ----
    int rA[2], rsA[2];
#pragma unroll
    for (int i = 0; i < 2; i++) {
        rA[i] = wm + i * 16 + (lane & 15);
        rsA[i] = (rA[i] >> 1) & 3;
    }
    int rB[4], rsB[4];
#pragma unroll
    for (int j2 = 0; j2 < 4; j2++) {
        rB[j2] = wn + j2 * 16 + ((lane >> 4) & 1) * 8 + (lane & 7);
        rsB[j2] = (rB[j2] >> 1) & 3;
    }
    int chA_lo = (lane >> 4);        // 0/1
    int chB_lo = ((lane >> 3) & 1);  // 0/1

    float acc[2][8][4];
#pragma unroll
    for (int i = 0; i < 2; i++)
#pragma unroll
        for (int j = 0; j < 8; j++)
#pragma unroll
            for (int e = 0; e < 4; e++) acc[i][j][e] = 0.f;

    auto load_stage = [&](uint32_t st, int kc) {
        int k0 = kc * KC;
        size_t boffk = (size_t)(kc * 4) * OUT_F;   // 4 blocks per KC window
        cp16(st + ST_AH + aoff0, gAh + k0);
        cp16(st + ST_AH + aoff1, gAh + k0 + 8);
        cp16(st + ST_AL + aoff0, gAl + k0);
        cp16(st + ST_AL + aoff1, gAl + k0 + 8);
        cp16(st + ST_BH + aoff0, reinterpret_cast<const uint4*>(g_Wh) + bbase0 + boffk);
        cp16(st + ST_BH + aoff1, reinterpret_cast<const uint4*>(g_Wh) + bbase1 + boffk);
        cp16(st + ST_BL + aoff0, reinterpret_cast<const uint4*>(g_Wl) + bbase0 + boffk);
        cp16(st + ST_BL + aoff1, reinterpret_cast<const uint4*>(g_Wl) + bbase1 + boffk);
        asm volatile("cp.async.commit_group;");
    };

    // ---- prologue: fill STAGES-1 stages ----
#pragma unroll
    for (int s = 0; s < STAGES - 1; s++)
        load_stage(sb + s * STAGE_BYTES, s);

    for (int kc = 0; kc < NKC; kc++) {
        asm volatile("cp.async.wait_group %0;" :: "n"(STAGES - 2));
        __syncthreads();
        uint32_t st = sb + (kc % STAGES) * STAGE_BYTES;

#pragma unroll
        for (int ks = 0; ks < 2; ks++) {
            uint32_t Ah[2][4], Al[2][4];
#pragma unroll
            for (int i = 0; i < 2; i++) {
                int ch = ks * 2 + chA_lo;
                uint32_t off = (uint32_t)(rA[i] * 64 + ((ch ^ rsA[i]) << 4));
                ldsm4(Ah[i], st + ST_AH + off);
                ldsm4(Al[i], st + ST_AL + off);
            }
#pragma unroll
            for (int j2 = 0; j2 < 4; j2++) {
                uint32_t Bh[4], Bl[4];
                int ch = ks * 2 + chB_lo;
                uint32_t off = (uint32_t)(rB[j2] * 64 + ((ch ^ rsB[j2]) << 4));
                ldsm4(Bh, st + ST_BH + off);
                ldsm4(Bl, st + ST_BL + off);
                float* d00 = acc[0][j2 * 2];
                float* d01 = acc[0][j2 * 2 + 1];
                float* d10 = acc[1][j2 * 2];
                float* d11 = acc[1][j2 * 2 + 1];
                // term-major: same-accumulator reuse distance = 4 MMAs
                mma16816(d00, Ah[0], &Bh[0]);
                mma16816(d01, Ah[0], &Bh[2]);
                mma16816(d10, Ah[1], &Bh[0]);
                mma16816(d11, Ah[1], &Bh[2]);
                mma16816(d00, Ah[0], &Bl[0]);
                mma16816(d01, Ah[0], &Bl[2]);
                mma16816(d10, Ah[1], &Bl[0]);
                mma16816(d11, Ah[1], &Bl[2]);
                mma16816(d00, Al[0], &Bh[0]);
                mma16816(d01, Al[0], &Bh[2]);
                mma16816(d10, Al[1], &Bh[0]);
                mma16816(d11, Al[1], &Bh[2]);
            }
        }

        int nk = kc + STAGES - 1;
        if (nk < NKC)
            load_stage(sb + (nk % STAGES) * STAGE_BYTES, nk);
        else
            asm volatile("cp.async.commit_group;");
    }

    // ---- epilogue: bias add + fp32 stores ----
#pragma unroll
    for (int i = 0; i < 2; i++) {
        int r = m0 + wm + i * 16 + (lane >> 2);
        float* row0 = out + (size_t)r * OUT_F;
        float* row1 = row0 + (size_t)8 * OUT_F;
#pragma unroll
        for (int j = 0; j < 8; j++) {
            int c = n0 + wn + j * 8 + 2 * (lane & 3);
            float b0 = __ldg(&bias[c]), b1 = __ldg(&bias[c + 1]);
            float2 v0 = make_float2(acc[i][j][0] + b0, acc[i][j][1] + b1);
            float2 v1 = make_float2(acc[i][j][2] + b0, acc[i][j][3] + b1);
            *reinterpret_cast<float2*>(row0 + c) = v0;
            *reinterpret_cast<float2*>(row1 + c) = v1;
        }
    }
}

// ---------------- launch -----------------------------------------------------
extern "C" void kernel_launch(void* const* d_in, const int* in_sizes, int n_in,
                              void* d_out, int out_size) {
    const float* x           = (const float*)d_in[0];
    const float* centroids   = (const float*)d_in[1];
    const float* bias        = (const float*)d_in[2];
    const int*   assignments = (const int*)d_in[3];
    float* out = (float*)d_out;

    cudaFuncSetAttribute(gemm_kernel,
                         cudaFuncAttributeMaxDynamicSharedMemorySize, SMEM_TOTAL);

    prep_kernel<<<PREP_X_BLOCKS + PREP_W_BLOCKS, 256>>>(x, centroids, assignments);
    gemm_kernel<<<dim3(OUT_F / TN, N_TOKENS / TM), 256, SMEM_TOTAL>>>(bias, out);
}